// round 14
// baseline (speedup 1.0000x reference)
#include <cuda_runtime.h>
#include <cuda_fp16.h>
#include <math.h>
#include <stdint.h>

// ---------------- problem constants ----------------
constexpr int NODES = 50000;
constexpr int EDGES = 800000;
constexpr int E2    = EDGES + NODES;   // 850000
constexpr int OUTC  = 64;
constexpr int HC    = 256;             // 4 heads * 64
constexpr int NC    = 10;
constexpr float NEG = 0.2f;
constexpr int NB_SCAN = (NODES + 1023) / 1024;  // 49

// ---------------- scratch (features in fp16) ----------------
__device__ __half g_xh [(size_t)NODES * HC];    // x converted to fp16
__device__ __half g_xl1[(size_t)NODES * HC];
__device__ __half g_xr1[(size_t)NODES * HC];
__device__ __half g_h1 [(size_t)NODES * HC];
__device__ __half g_xl2[(size_t)NODES * OUTC];
__device__ __half g_xr2[(size_t)NODES * OUTC];
__device__ int   g_deg[NODES];
__device__ int   g_rowptr[NODES + 1];
__device__ int   g_cursor[NODES];
__device__ int   g_csrc[E2];
// transposed + fp16 hi/lo split weights
__device__ __half g_bt1_hi[512 * 256];
__device__ __half g_bt1_lo[512 * 256];
__device__ __half g_bt2_hi[128 * 256];
__device__ __half g_bt2_lo[128 * 256];

__device__ __forceinline__ float lrelu(float v) { return v > 0.f ? v : NEG * v; }

__device__ __forceinline__ uint32_t smem_u32(const void* p) {
    uint32_t a;
    asm("{ .reg .u64 t; cvta.to.shared.u64 t, %1; cvt.u32.u64 %0, t; }" : "=r"(a) : "l"(p));
    return a;
}

__device__ __forceinline__ void ldsm_x4(uint32_t* r, uint32_t addr) {
    asm volatile("ldmatrix.sync.aligned.m8n8.x4.shared.b16 {%0,%1,%2,%3}, [%4];"
                 : "=r"(r[0]), "=r"(r[1]), "=r"(r[2]), "=r"(r[3]) : "r"(addr));
}
__device__ __forceinline__ void ldsm_x2(uint32_t* r, uint32_t addr) {
    asm volatile("ldmatrix.sync.aligned.m8n8.x2.shared.b16 {%0,%1}, [%2];"
                 : "=r"(r[0]), "=r"(r[1]) : "r"(addr));
}
__device__ __forceinline__ void mma_fp16(float* c, const uint32_t* a, const uint32_t* b) {
    asm volatile("mma.sync.aligned.m16n8k16.row.col.f32.f16.f16.f32 "
                 "{%0,%1,%2,%3}, {%4,%5,%6,%7}, {%8,%9}, {%0,%1,%2,%3};"
                 : "+f"(c[0]), "+f"(c[1]), "+f"(c[2]), "+f"(c[3])
                 : "r"(a[0]), "r"(a[1]), "r"(a[2]), "r"(a[3]), "r"(b[0]), "r"(b[1]));
}

// half2 LeakyReLU (valid for NEG>0: max(v, NEG*v) == lrelu(v))
__device__ __forceinline__ __half2 lrelu2(__half2 v, __half2 neg) {
    return __hmax2(v, __hmul2(v, neg));
}

// ---------------- x -> fp16 conversion (identical rounding to gemm's sstore) ----------------
__global__ void k_cvt_x(const float* __restrict__ x, __half* __restrict__ xh) {
    int t = blockIdx.x * blockDim.x + threadIdx.x;
    constexpr int TOTAL8 = NODES * HC / 8;   // 1.6M
    if (t >= TOTAL8) return;
    const float4* p = (const float4*)x + 2 * (size_t)t;
    float4 v0 = p[0], v1 = p[1];
    __half2 h[4];
    h[0] = __floats2half2_rn(v0.x, v0.y);
    h[1] = __floats2half2_rn(v0.z, v0.w);
    h[2] = __floats2half2_rn(v1.x, v1.y);
    h[3] = __floats2half2_rn(v1.z, v1.w);
    *((uint4*)xh + t) = *(uint4*)h;
}

// ---------------- weight prep: transpose + fp16 hi/lo split ----------------
__global__ void k_prep_B(const float* __restrict__ W0, const float* __restrict__ W1,
                         __half* __restrict__ bt_hi, __half* __restrict__ bt_lo,
                         int N, int K) {
    int t = blockIdx.x * blockDim.x + threadIdx.x;
    int total = 2 * N * K;
    if (t >= total) return;
    int mat = t / (N * K);
    int r = t - mat * (N * K);
    int n = r / K, k = r - n * K;
    const float* W = mat ? W1 : W0;
    float w = W[k * N + n];
    __half hi = __float2half_rn(w);
    bt_hi[t] = hi;
    bt_lo[t] = __float2half_rn(w - __half2float(hi));
}

// ---------------- fp16x2 tensor-core GEMM (mma.sync), fp16 in/out ----------------
template <int NBM>
__global__ void __launch_bounds__(256, 1) gemm_mma(const __half* __restrict__ A,
                                                   const __half* __restrict__ Bh,
                                                   const __half* __restrict__ Bl,
                                                   __half* __restrict__ C0,
                                                   __half* __restrict__ C1,
                                                   int M) {
    constexpr int K = 256;
    constexpr int LDS = 40;
    __shared__ __half sAh[128 * LDS];
    __shared__ __half sBh[128 * LDS];
    __shared__ __half sBl[128 * LDS];

    int tid = threadIdx.x;
    int lane = tid & 31;
    int wid = tid >> 5;
    int warpM = wid >> 2;
    int warpN = wid & 3;
    int m0 = blockIdx.y * 128;
    int n0 = blockIdx.x * 128;

    uint32_t bAh = smem_u32(sAh);
    uint32_t bBh = smem_u32(sBh), bBl = smem_u32(sBl);

    uint4 apfh[2];
    int4 bhpf[2], blpf[2];

    auto gload = [&](int kb) {
#pragma unroll
        for (int i = 0; i < 2; i++) {
            int u = tid + 256 * i;
            int row = u >> 2, c8 = u & 3;
            apfh[i] = make_uint4(0, 0, 0, 0);
            if (m0 + row < M)
                apfh[i] = *(const uint4*)(A + (size_t)(m0 + row) * K + kb * 32 + c8 * 8);
        }
#pragma unroll
        for (int i = 0; i < 2; i++) {
            int u = tid + 256 * i;
            int row = u >> 2, c = u & 3;
            size_t g = (size_t)(n0 + row) * K + kb * 32 + c * 8;
            bhpf[i] = *(const int4*)(Bh + g);
            blpf[i] = *(const int4*)(Bl + g);
        }
    };

    auto sstore = [&]() {
#pragma unroll
        for (int i = 0; i < 2; i++) {
            int u = tid + 256 * i;
            int row = u >> 2, c8 = u & 3;
            *(uint4*)(sAh + row * LDS + c8 * 8) = apfh[i];
        }
#pragma unroll
        for (int i = 0; i < 2; i++) {
            int u = tid + 256 * i;
            int row = u >> 2, c = u & 3;
            int e = row * LDS + c * 8;
            *(int4*)(sBh + e) = bhpf[i];
            *(int4*)(sBl + e) = blpf[i];
        }
    };

    float acc[4][4][4];
#pragma unroll
    for (int f = 0; f < 4; f++)
#pragma unroll
        for (int g = 0; g < 4; g++)
#pragma unroll
            for (int q = 0; q < 4; q++) acc[f][g][q] = 0.f;

    int arow = warpM * 64 + (lane & 15);
    int akc  = (lane >> 4) << 3;
    int brow = warpN * 32 + (lane & 7);
    int bkc  = ((lane >> 3) & 1) << 3;

    gload(0);
    for (int kb = 0; kb < 8; kb++) {
        sstore();
        __syncthreads();
        if (kb < 7) gload(kb + 1);

#pragma unroll
        for (int kk = 0; kk < 2; kk++) {
            uint32_t aoff = (uint32_t)((arow * LDS + kk * 16 + akc) * 2);
            uint32_t boff = (uint32_t)((brow * LDS + kk * 16 + bkc) * 2);

            uint32_t ah[4][4], bh[4][2];
#pragma unroll
            for (int f = 0; f < 4; f++)
                ldsm_x4(ah[f], bAh + aoff + (uint32_t)(f * 16 * LDS * 2));
#pragma unroll
            for (int g = 0; g < 4; g++)
                ldsm_x2(bh[g], bBh + boff + (uint32_t)(g * 8 * LDS * 2));
#pragma unroll
            for (int f = 0; f < 4; f++)
#pragma unroll
                for (int g = 0; g < 4; g++)
                    mma_fp16(acc[f][g], ah[f], bh[g]);

            uint32_t bl[4][2];
#pragma unroll
            for (int g = 0; g < 4; g++)
                ldsm_x2(bl[g], bBl + boff + (uint32_t)(g * 8 * LDS * 2));
#pragma unroll
            for (int f = 0; f < 4; f++)
#pragma unroll
                for (int g = 0; g < 4; g++)
                    mma_fp16(acc[f][g], ah[f], bl[g]);
        }
        __syncthreads();
    }

#pragma unroll
    for (int f = 0; f < 4; f++) {
#pragma unroll
        for (int g = 0; g < 4; g++) {
            int row = m0 + warpM * 64 + f * 16 + (lane >> 2);
            int col = n0 + warpN * 32 + g * 8 + (lane & 3) * 2;
            int mat = col / NBM;
            int cc = col - mat * NBM;
            __half* Cp = mat ? C1 : C0;
            if (row < M) {
                __half2 v;
                v.x = __float2half_rn(acc[f][g][0]);
                v.y = __float2half_rn(acc[f][g][1]);
                *(__half2*)(Cp + (size_t)row * NBM + cc) = v;
            }
            if (row + 8 < M) {
                __half2 v;
                v.x = __float2half_rn(acc[f][g][2]);
                v.y = __float2half_rn(acc[f][g][3]);
                *(__half2*)(Cp + (size_t)(row + 8) * NBM + cc) = v;
            }
        }
    }
}

// ---------------- CSR build ----------------
__global__ void k_hist(const int* __restrict__ ei) {
    int t = blockIdx.x * blockDim.x + threadIdx.x;
    int e4 = t * 4;
    if (e4 + 3 < EDGES) {
        int4 d = *(const int4*)(ei + EDGES + e4);
        atomicAdd(&g_deg[d.x], 1);
        atomicAdd(&g_deg[d.y], 1);
        atomicAdd(&g_deg[d.z], 1);
        atomicAdd(&g_deg[d.w], 1);
    } else if (e4 < EDGES) {
        for (int e = e4; e < EDGES; e++) atomicAdd(&g_deg[ei[EDGES + e]], 1);
    }
}

__global__ void __launch_bounds__(1024) k_scan_all() {
    __shared__ int wsum[32];
    int tid = threadIdx.x;
    int lane = tid & 31, w = tid >> 5;
    int running = 0;
    for (int chunk = 0; chunk < NB_SCAN; chunk++) {
        int i = chunk * 1024 + tid;
        int v = (i < NODES) ? (g_deg[i] + 1) : 0;   // +1 = self loop
        int x = v;
#pragma unroll
        for (int d = 1; d < 32; d <<= 1) {
            int y = __shfl_up_sync(0xffffffffu, x, d);
            if (lane >= d) x += y;
        }
        if (lane == 31) wsum[w] = x;
        __syncthreads();
        if (w == 0) {
            int tsum = wsum[lane];
#pragma unroll
            for (int d = 1; d < 32; d <<= 1) {
                int y = __shfl_up_sync(0xffffffffu, tsum, d);
                if (lane >= d) tsum += y;
            }
            wsum[lane] = tsum;
        }
        __syncthreads();
        int incl = x + (w > 0 ? wsum[w - 1] : 0) + running;
        if (i < NODES) {
            g_rowptr[i] = incl - v;
            g_cursor[i] = incl - v;
            if (i == NODES - 1) g_rowptr[NODES] = incl;
        }
        running += wsum[31];
        __syncthreads();
    }
}

__global__ void k_fill(const int* __restrict__ ei) {
    int t = blockIdx.x * blockDim.x + threadIdx.x;
    constexpr int EQ = EDGES / 4;
    if (t < EQ) {
        int e4 = t * 4;
        int4 s = *(const int4*)(ei + e4);
        int4 d = *(const int4*)(ei + EDGES + e4);
        g_csrc[atomicAdd(&g_cursor[d.x], 1)] = s.x;
        g_csrc[atomicAdd(&g_cursor[d.y], 1)] = s.y;
        g_csrc[atomicAdd(&g_cursor[d.z], 1)] = s.z;
        g_csrc[atomicAdd(&g_cursor[d.w], 1)] = s.w;
    } else if (t < EQ + NODES) {
        int i = t - EQ;
        g_csrc[atomicAdd(&g_cursor[i], 1)] = i;
    }
}

// ---------------- fused GATv2 aggregation, layer 1 (H=4, C=64) ----------------
// One warp per node, explicit 2-edge unroll, no max-subtraction.
// Attention input add + LeakyReLU in half2; dot/exp/value-accum in fp32.
__global__ void __launch_bounds__(256) k_agg1(const int* __restrict__ rowptr,
                                              const int* __restrict__ csrc,
                                              const __half* __restrict__ xl,
                                              const __half* __restrict__ xr,
                                              const float* __restrict__ att,
                                              const float* __restrict__ bias,
                                              __half* __restrict__ out) {
    int warp = (blockIdx.x * blockDim.x + threadIdx.x) >> 5;
    int lane = threadIdx.x & 31;
    if (warp >= NODES) return;
    int n = warp;
    int off = lane * 8;

    uint4 rraw = *(const uint4*)(xr + (size_t)n * HC + off);
    __half2 rr2[4];
    *(uint4*)rr2 = rraw;
    const float4* pa = (const float4*)(att + off);
    float4 a0 = pa[0], a1 = pa[1];
    float aw[8] = {a0.x, a0.y, a0.z, a0.w, a1.x, a1.y, a1.z, a1.w};
    const __half2 neg2 = __float2half2_rn(NEG);

    float s = 0.f;
    float acc[8] = {0.f, 0.f, 0.f, 0.f, 0.f, 0.f, 0.f, 0.f};

    int b = rowptr[n], e = rowptr[n + 1];
    for (int kb = b; kb < e; kb += 32) {
        int idx = kb + lane;
        int mysrc = (idx < e) ? csrc[idx] : 0;
        int cnt = min(32, e - kb);
        int j = 0;
        for (; j + 1 < cnt; j += 2) {
            int s0 = __shfl_sync(0xffffffffu, mysrc, j);
            int s1 = __shfl_sync(0xffffffffu, mysrc, j + 1);
            uint4 uraw = *(const uint4*)(xl + (size_t)s0 * HC + off);
            uint4 traw = *(const uint4*)(xl + (size_t)s1 * HC + off);
            __half2* uh = (__half2*)&uraw;
            __half2* th = (__half2*)&traw;
            float q0 = 0.f, q1 = 0.f;
            float uf[8], tf[8];
#pragma unroll
            for (int i = 0; i < 4; i++) {
                float2 lu = __half22float2(lrelu2(__hadd2(uh[i], rr2[i]), neg2));
                float2 lt = __half22float2(lrelu2(__hadd2(th[i], rr2[i]), neg2));
                float2 vu = __half22float2(uh[i]);
                float2 vt = __half22float2(th[i]);
                uf[2 * i] = vu.x; uf[2 * i + 1] = vu.y;
                tf[2 * i] = vt.x; tf[2 * i + 1] = vt.y;
                q0 = fmaf(lu.x, aw[2 * i], q0);
                q0 = fmaf(lu.y, aw[2 * i + 1], q0);
                q1 = fmaf(lt.x, aw[2 * i], q1);
                q1 = fmaf(lt.y, aw[2 * i + 1], q1);
            }
            q0 += __shfl_xor_sync(0xffffffffu, q0, 1);
            q1 += __shfl_xor_sync(0xffffffffu, q1, 1);
            q0 += __shfl_xor_sync(0xffffffffu, q0, 2);
            q1 += __shfl_xor_sync(0xffffffffu, q1, 2);
            q0 += __shfl_xor_sync(0xffffffffu, q0, 4);
            q1 += __shfl_xor_sync(0xffffffffu, q1, 4);
            float w0 = __expf(q0), w1 = __expf(q1);
            s += w0 + w1;
#pragma unroll
            for (int q = 0; q < 8; q++)
                acc[q] += w0 * uf[q] + w1 * tf[q];
        }
        if (j < cnt) {
            int s0 = __shfl_sync(0xffffffffu, mysrc, j);
            uint4 uraw = *(const uint4*)(xl + (size_t)s0 * HC + off);
            __half2* uh = (__half2*)&uraw;
            float q0 = 0.f;
            float uf[8];
#pragma unroll
            for (int i = 0; i < 4; i++) {
                float2 lu = __half22float2(lrelu2(__hadd2(uh[i], rr2[i]), neg2));
                float2 vu = __half22float2(uh[i]);
                uf[2 * i] = vu.x; uf[2 * i + 1] = vu.y;
                q0 = fmaf(lu.x, aw[2 * i], q0);
                q0 = fmaf(lu.y, aw[2 * i + 1], q0);
            }
            q0 += __shfl_xor_sync(0xffffffffu, q0, 1);
            q0 += __shfl_xor_sync(0xffffffffu, q0, 2);
            q0 += __shfl_xor_sync(0xffffffffu, q0, 4);
            float w0 = __expf(q0);
            s += w0;
#pragma unroll
            for (int q = 0; q < 8; q++)
                acc[q] += w0 * uf[q];
        }
    }
    float inv = 1.0f / s;
    const float4* pb = (const float4*)(bias + off);
    float4 b0 = pb[0], b1 = pb[1];
    float bw[8] = {b0.x, b0.y, b0.z, b0.w, b1.x, b1.y, b1.z, b1.w};
    __half hv[8];
#pragma unroll
    for (int q = 0; q < 8; q++)
        hv[q] = __float2half_rn(fmaxf(acc[q] * inv + bw[q], 0.f));
    *(uint4*)(out + (size_t)n * HC + off) = *(uint4*)hv;
}

// ---------------- fused GATv2 aggregation layer 2 + final linear ----------------
// half2 add+lrelu; dot/exp/value in fp32.
__global__ void __launch_bounds__(256) k_agg2(const int* __restrict__ rowptr,
                                              const int* __restrict__ csrc,
                                              const __half* __restrict__ xl,
                                              const __half* __restrict__ xr,
                                              const float* __restrict__ att,
                                              const float* __restrict__ bias,
                                              const float* __restrict__ Wlin,
                                              const float* __restrict__ blin,
                                              float* __restrict__ out) {
    int warp = (blockIdx.x * blockDim.x + threadIdx.x) >> 5;
    int lane = threadIdx.x & 31;
    if (warp >= NODES) return;
    int n = warp;
    int off = lane * 2;

    __half2 rrh = *(const __half2*)(xr + (size_t)n * OUTC + off);
    float2 a = *(const float2*)(att + off);
    const __half2 neg2 = __float2half2_rn(NEG);

    float s = 0.f;
    float acc0 = 0.f, acc1 = 0.f;

    int b = rowptr[n], e = rowptr[n + 1];
    for (int kb = b; kb < e; kb += 32) {
        int idx = kb + lane;
        int mysrc = (idx < e) ? csrc[idx] : 0;
        int cnt = min(32, e - kb);
        int j = 0;
        for (; j + 1 < cnt; j += 2) {
            int s0 = __shfl_sync(0xffffffffu, mysrc, j);
            int s1 = __shfl_sync(0xffffffffu, mysrc, j + 1);
            __half2 uh0 = *(const __half2*)(xl + (size_t)s0 * OUTC + off);
            __half2 uh1 = *(const __half2*)(xl + (size_t)s1 * OUTC + off);
            float2 l0 = __half22float2(lrelu2(__hadd2(uh0, rrh), neg2));
            float2 l1 = __half22float2(lrelu2(__hadd2(uh1, rrh), neg2));
            float2 v0 = __half22float2(uh0);
            float2 v1 = __half22float2(uh1);
            float q0 = l0.x * a.x + l0.y * a.y;
            float q1 = l1.x * a.x + l1.y * a.y;
#pragma unroll
            for (int d = 1; d < 32; d <<= 1) {
                q0 += __shfl_xor_sync(0xffffffffu, q0, d);
                q1 += __shfl_xor_sync(0xffffffffu, q1, d);
            }
            float w0 = __expf(q0), w1 = __expf(q1);
            s += w0 + w1;
            acc0 += w0 * v0.x + w1 * v1.x;
            acc1 += w0 * v0.y + w1 * v1.y;
        }
        if (j < cnt) {
            int s0 = __shfl_sync(0xffffffffu, mysrc, j);
            __half2 uh0 = *(const __half2*)(xl + (size_t)s0 * OUTC + off);
            float2 l0 = __half22float2(lrelu2(__hadd2(uh0, rrh), neg2));
            float2 v0 = __half22float2(uh0);
            float q0 = l0.x * a.x + l0.y * a.y;
#pragma unroll
            for (int d = 1; d < 32; d <<= 1)
                q0 += __shfl_xor_sync(0xffffffffu, q0, d);
            float w0 = __expf(q0);
            s += w0;
            acc0 += w0 * v0.x;
            acc1 += w0 * v0.y;
        }
    }
    float inv = 1.0f / s;
    float2 bb = *(const float2*)(bias + off);
    float hx = fmaxf(acc0 * inv + bb.x, 0.f);
    float hy = fmaxf(acc1 * inv + bb.y, 0.f);

    float part[NC];
#pragma unroll
    for (int c = 0; c < NC; c++)
        part[c] = hx * Wlin[off * NC + c] + hy * Wlin[(off + 1) * NC + c];
#pragma unroll
    for (int d = 16; d >= 1; d >>= 1)
#pragma unroll
        for (int c = 0; c < NC; c++)
            part[c] += __shfl_xor_sync(0xffffffffu, part[c], d);
    if (lane == 0) {
#pragma unroll
        for (int c = 0; c < NC; c++)
            out[(size_t)n * NC + c] = part[c] + blin[c];
    }
}

// ---------------- launch ----------------
extern "C" void kernel_launch(void* const* d_in, const int* in_sizes, int n_in,
                              void* d_out, int out_size) {
    const float* x    = (const float*)d_in[0];
    const int*   ei   = (const int*)d_in[1];
    const float* Wl1  = (const float*)d_in[2];
    const float* Wr1  = (const float*)d_in[3];
    const float* att1 = (const float*)d_in[4];
    const float* b1   = (const float*)d_in[5];
    const float* Wl2  = (const float*)d_in[6];
    const float* Wr2  = (const float*)d_in[7];
    const float* att2 = (const float*)d_in[8];
    const float* b2   = (const float*)d_in[9];
    const float* Wlin = (const float*)d_in[10];
    const float* blin = (const float*)d_in[11];
    float* out = (float*)d_out;

    __half *xh, *xl1, *xr1, *h1, *xl2, *xr2;
    __half *bt1h, *bt1l, *bt2h, *bt2l;
    int *rowptr, *csrc, *deg;
    cudaGetSymbolAddress((void**)&xh,  g_xh);
    cudaGetSymbolAddress((void**)&xl1, g_xl1);
    cudaGetSymbolAddress((void**)&xr1, g_xr1);
    cudaGetSymbolAddress((void**)&h1,  g_h1);
    cudaGetSymbolAddress((void**)&xl2, g_xl2);
    cudaGetSymbolAddress((void**)&xr2, g_xr2);
    cudaGetSymbolAddress((void**)&rowptr, g_rowptr);
    cudaGetSymbolAddress((void**)&csrc,   g_csrc);
    cudaGetSymbolAddress((void**)&deg,    g_deg);
    cudaGetSymbolAddress((void**)&bt1h, g_bt1_hi);
    cudaGetSymbolAddress((void**)&bt1l, g_bt1_lo);
    cudaGetSymbolAddress((void**)&bt2h, g_bt2_hi);
    cudaGetSymbolAddress((void**)&bt2l, g_bt2_lo);

    static cudaStream_t s2 = nullptr;
    static cudaEvent_t ev_fork = nullptr, ev_cvt = nullptr, ev_join = nullptr;
    if (!s2) {
        cudaStreamCreateWithFlags(&s2, cudaStreamNonBlocking);
        cudaEventCreateWithFlags(&ev_fork, cudaEventDisableTiming);
        cudaEventCreateWithFlags(&ev_cvt,  cudaEventDisableTiming);
        cudaEventCreateWithFlags(&ev_join, cudaEventDisableTiming);
    }

    int mrows = (NODES + 127) / 128;   // 391

    // ---- fork: x-conversion + CSR build + layer-2 weight prep on s2 ----
    cudaEventRecord(ev_fork, 0);
    cudaStreamWaitEvent(s2, ev_fork, 0);

    k_cvt_x<<<(NODES * HC / 8 + 255) / 256, 256, 0, s2>>>(x, xh);
    cudaEventRecord(ev_cvt, s2);
    cudaMemsetAsync(deg, 0, NODES * sizeof(int), s2);
    k_hist<<<(EDGES / 4 + 255) / 256, 256, 0, s2>>>(ei);
    k_scan_all<<<1, 1024, 0, s2>>>();
    k_fill<<<(EDGES / 4 + NODES + 255) / 256, 256, 0, s2>>>(ei);
    k_prep_B<<<(2 * 64 * 256 + 255) / 256, 256, 0, s2>>>(Wl2, Wr2, bt2h, bt2l, 64, 256);
    cudaEventRecord(ev_join, s2);

    // main: prep1 runs concurrently with cvt_x; gemm1 needs both
    k_prep_B<<<(2 * 256 * 256 + 255) / 256, 256>>>(Wl1, Wr1, bt1h, bt1l, 256, 256);
    cudaStreamWaitEvent(0, ev_cvt, 0);
    gemm_mma<256><<<dim3(4, mrows), 256>>>(xh, bt1h, bt1l, xl1, xr1, NODES);

    cudaStreamWaitEvent(0, ev_join, 0);

    k_agg1<<<(NODES + 7) / 8, 256>>>(rowptr, csrc, xl1, xr1, att1, b1, h1);
    gemm_mma<64><<<dim3(1, mrows), 256>>>(h1, bt2h, bt2l, xl2, xr2, NODES);
    k_agg2<<<(NODES + 7) / 8, 256>>>(rowptr, csrc, xl2, xr2, att2, b2, Wlin, blin, out);
}

// round 15
// speedup vs baseline: 1.1329x; 1.1329x over previous
#include <cuda_runtime.h>
#include <cuda_fp16.h>
#include <math.h>
#include <stdint.h>

// ---------------- problem constants ----------------
constexpr int NODES = 50000;
constexpr int EDGES = 800000;
constexpr int E2    = EDGES + NODES;   // 850000
constexpr int OUTC  = 64;
constexpr int HC    = 256;             // 4 heads * 64
constexpr int NC    = 10;
constexpr float NEG = 0.2f;
constexpr int NB_SCAN = (NODES + 1023) / 1024;  // 49

// ---------------- scratch (features in fp16) ----------------
__device__ __half g_xl1[(size_t)NODES * HC];
__device__ __half g_xr1[(size_t)NODES * HC];
__device__ __half g_h1 [(size_t)NODES * HC];
__device__ __half g_xl2[(size_t)NODES * OUTC];
__device__ __half g_xr2[(size_t)NODES * OUTC];
__device__ int   g_deg[NODES];
__device__ int   g_rowptr[NODES + 1];
__device__ int   g_cursor[NODES];
__device__ int   g_csrc[E2];
// transposed + fp16 hi/lo split weights
__device__ __half g_bt1_hi[512 * 256];
__device__ __half g_bt1_lo[512 * 256];
__device__ __half g_bt2_hi[128 * 256];
__device__ __half g_bt2_lo[128 * 256];

__device__ __forceinline__ float lrelu(float v) { return v > 0.f ? v : NEG * v; }

__device__ __forceinline__ uint32_t smem_u32(const void* p) {
    uint32_t a;
    asm("{ .reg .u64 t; cvta.to.shared.u64 t, %1; cvt.u32.u64 %0, t; }" : "=r"(a) : "l"(p));
    return a;
}

__device__ __forceinline__ void ldsm_x4(uint32_t* r, uint32_t addr) {
    asm volatile("ldmatrix.sync.aligned.m8n8.x4.shared.b16 {%0,%1,%2,%3}, [%4];"
                 : "=r"(r[0]), "=r"(r[1]), "=r"(r[2]), "=r"(r[3]) : "r"(addr));
}
__device__ __forceinline__ void ldsm_x2(uint32_t* r, uint32_t addr) {
    asm volatile("ldmatrix.sync.aligned.m8n8.x2.shared.b16 {%0,%1}, [%2];"
                 : "=r"(r[0]), "=r"(r[1]) : "r"(addr));
}
__device__ __forceinline__ void mma_fp16(float* c, const uint32_t* a, const uint32_t* b) {
    asm volatile("mma.sync.aligned.m16n8k16.row.col.f32.f16.f16.f32 "
                 "{%0,%1,%2,%3}, {%4,%5,%6,%7}, {%8,%9}, {%0,%1,%2,%3};"
                 : "+f"(c[0]), "+f"(c[1]), "+f"(c[2]), "+f"(c[3])
                 : "r"(a[0]), "r"(a[1]), "r"(a[2]), "r"(a[3]), "r"(b[0]), "r"(b[1]));
}

// half2 LeakyReLU (valid for NEG>0: max(v, NEG*v) == lrelu(v))
__device__ __forceinline__ __half2 lrelu2(__half2 v, __half2 neg) {
    return __hmax2(v, __hmul2(v, neg));
}

// ---------------- weight prep: transpose + fp16 hi/lo split ----------------
__global__ void k_prep_B(const float* __restrict__ W0, const float* __restrict__ W1,
                         __half* __restrict__ bt_hi, __half* __restrict__ bt_lo,
                         int N, int K) {
    int t = blockIdx.x * blockDim.x + threadIdx.x;
    int total = 2 * N * K;
    if (t >= total) return;
    int mat = t / (N * K);
    int r = t - mat * (N * K);
    int n = r / K, k = r - n * K;
    const float* W = mat ? W1 : W0;
    float w = W[k * N + n];
    __half hi = __float2half_rn(w);
    bt_hi[t] = hi;
    bt_lo[t] = __float2half_rn(w - __half2float(hi));
}

// ---------------- fp16x2 tensor-core GEMM (mma.sync), double-buffered ----------------
template <int NBM, typename AT>
__global__ void __launch_bounds__(256, 1) gemm_mma(const AT* __restrict__ A,
                                                   const __half* __restrict__ Bh,
                                                   const __half* __restrict__ Bl,
                                                   __half* __restrict__ C0,
                                                   __half* __restrict__ C1,
                                                   int M) {
    constexpr int K = 256;
    constexpr int LDS = 40;
    constexpr int STG = 128 * LDS;           // elements per stage
    constexpr bool AHALF = (sizeof(AT) == 2);
    __shared__ __half sAh[2 * STG];
    __shared__ __half sBh[2 * STG];
    __shared__ __half sBl[2 * STG];

    int tid = threadIdx.x;
    int lane = tid & 31;
    int wid = tid >> 5;
    int warpM = wid >> 2;
    int warpN = wid & 3;
    int m0 = blockIdx.y * 128;
    int n0 = blockIdx.x * 128;

    uint32_t bAh = smem_u32(sAh);
    uint32_t bBh = smem_u32(sBh), bBl = smem_u32(sBl);

    float4 apf[4];
    uint4  apfh[2];
    int4 bhpf[2], blpf[2];

    auto gload = [&](int kb) {
        if constexpr (!AHALF) {
#pragma unroll
            for (int i = 0; i < 4; i++) {
                int u = tid + 256 * i;
                int row = u >> 3, c4 = u & 7;
                apf[i] = make_float4(0.f, 0.f, 0.f, 0.f);
                if (m0 + row < M)
                    apf[i] = *(const float4*)((const float*)A + (size_t)(m0 + row) * K + kb * 32 + c4 * 4);
            }
        } else {
#pragma unroll
            for (int i = 0; i < 2; i++) {
                int u = tid + 256 * i;
                int row = u >> 2, c8 = u & 3;
                apfh[i] = make_uint4(0, 0, 0, 0);
                if (m0 + row < M)
                    apfh[i] = *(const uint4*)((const __half*)A + (size_t)(m0 + row) * K + kb * 32 + c8 * 8);
            }
        }
#pragma unroll
        for (int i = 0; i < 2; i++) {
            int u = tid + 256 * i;
            int row = u >> 2, c = u & 3;
            size_t g = (size_t)(n0 + row) * K + kb * 32 + c * 8;
            bhpf[i] = *(const int4*)(Bh + g);
            blpf[i] = *(const int4*)(Bl + g);
        }
    };

    auto sstore = [&](int st) {
        int so = st * STG;
        if constexpr (!AHALF) {
#pragma unroll
            for (int i = 0; i < 4; i++) {
                int u = tid + 256 * i;
                int row = u >> 3, c4 = u & 7;
                float4 v = apf[i];
                __half2 h0, h1;
                h0.x = __float2half_rn(v.x);
                h0.y = __float2half_rn(v.y);
                h1.x = __float2half_rn(v.z);
                h1.y = __float2half_rn(v.w);
                int e = so + row * LDS + c4 * 4;
                *(__half2*)(sAh + e)     = h0;
                *(__half2*)(sAh + e + 2) = h1;
            }
        } else {
#pragma unroll
            for (int i = 0; i < 2; i++) {
                int u = tid + 256 * i;
                int row = u >> 2, c8 = u & 3;
                *(uint4*)(sAh + so + row * LDS + c8 * 8) = apfh[i];
            }
        }
#pragma unroll
        for (int i = 0; i < 2; i++) {
            int u = tid + 256 * i;
            int row = u >> 2, c = u & 3;
            int e = so + row * LDS + c * 8;
            *(int4*)(sBh + e) = bhpf[i];
            *(int4*)(sBl + e) = blpf[i];
        }
    };

    float acc[4][4][4];
#pragma unroll
    for (int f = 0; f < 4; f++)
#pragma unroll
        for (int g = 0; g < 4; g++)
#pragma unroll
            for (int q = 0; q < 4; q++) acc[f][g][q] = 0.f;

    int arow = warpM * 64 + (lane & 15);
    int akc  = (lane >> 4) << 3;
    int brow = warpN * 32 + (lane & 7);
    int bkc  = ((lane >> 3) & 1) << 3;

    gload(0);
    sstore(0);
    __syncthreads();

    for (int kb = 0; kb < 8; kb++) {
        int cur = kb & 1;
        if (kb < 7) gload(kb + 1);

        uint32_t stoff = (uint32_t)(cur * STG * 2);
#pragma unroll
        for (int kk = 0; kk < 2; kk++) {
            uint32_t aoff = stoff + (uint32_t)((arow * LDS + kk * 16 + akc) * 2);
            uint32_t boff = stoff + (uint32_t)((brow * LDS + kk * 16 + bkc) * 2);

            uint32_t ah[4][4], bh[4][2];
#pragma unroll
            for (int f = 0; f < 4; f++)
                ldsm_x4(ah[f], bAh + aoff + (uint32_t)(f * 16 * LDS * 2));
#pragma unroll
            for (int g = 0; g < 4; g++)
                ldsm_x2(bh[g], bBh + boff + (uint32_t)(g * 8 * LDS * 2));
#pragma unroll
            for (int f = 0; f < 4; f++)
#pragma unroll
                for (int g = 0; g < 4; g++)
                    mma_fp16(acc[f][g], ah[f], bh[g]);

            uint32_t bl[4][2];
#pragma unroll
            for (int g = 0; g < 4; g++)
                ldsm_x2(bl[g], bBl + boff + (uint32_t)(g * 8 * LDS * 2));
#pragma unroll
            for (int f = 0; f < 4; f++)
#pragma unroll
                for (int g = 0; g < 4; g++)
                    mma_fp16(acc[f][g], ah[f], bl[g]);
        }

        if (kb < 7) sstore((kb + 1) & 1);
        __syncthreads();
    }

#pragma unroll
    for (int f = 0; f < 4; f++) {
#pragma unroll
        for (int g = 0; g < 4; g++) {
            int row = m0 + warpM * 64 + f * 16 + (lane >> 2);
            int col = n0 + warpN * 32 + g * 8 + (lane & 3) * 2;
            int mat = col / NBM;
            int cc = col - mat * NBM;
            __half* Cp = mat ? C1 : C0;
            if (row < M) {
                __half2 v;
                v.x = __float2half_rn(acc[f][g][0]);
                v.y = __float2half_rn(acc[f][g][1]);
                *(__half2*)(Cp + (size_t)row * NBM + cc) = v;
            }
            if (row + 8 < M) {
                __half2 v;
                v.x = __float2half_rn(acc[f][g][2]);
                v.y = __float2half_rn(acc[f][g][3]);
                *(__half2*)(Cp + (size_t)(row + 8) * NBM + cc) = v;
            }
        }
    }
}

// ---------------- CSR build ----------------
__global__ void k_hist(const int* __restrict__ ei) {
    int t = blockIdx.x * blockDim.x + threadIdx.x;
    int e4 = t * 4;
    if (e4 + 3 < EDGES) {
        int4 d = *(const int4*)(ei + EDGES + e4);
        atomicAdd(&g_deg[d.x], 1);
        atomicAdd(&g_deg[d.y], 1);
        atomicAdd(&g_deg[d.z], 1);
        atomicAdd(&g_deg[d.w], 1);
    } else if (e4 < EDGES) {
        for (int e = e4; e < EDGES; e++) atomicAdd(&g_deg[ei[EDGES + e]], 1);
    }
}

__global__ void __launch_bounds__(1024) k_scan_all() {
    __shared__ int wsum[32];
    int tid = threadIdx.x;
    int lane = tid & 31, w = tid >> 5;
    int running = 0;
    for (int chunk = 0; chunk < NB_SCAN; chunk++) {
        int i = chunk * 1024 + tid;
        int v = (i < NODES) ? (g_deg[i] + 1) : 0;   // +1 = self loop
        int x = v;
#pragma unroll
        for (int d = 1; d < 32; d <<= 1) {
            int y = __shfl_up_sync(0xffffffffu, x, d);
            if (lane >= d) x += y;
        }
        if (lane == 31) wsum[w] = x;
        __syncthreads();
        if (w == 0) {
            int tsum = wsum[lane];
#pragma unroll
            for (int d = 1; d < 32; d <<= 1) {
                int y = __shfl_up_sync(0xffffffffu, tsum, d);
                if (lane >= d) tsum += y;
            }
            wsum[lane] = tsum;
        }
        __syncthreads();
        int incl = x + (w > 0 ? wsum[w - 1] : 0) + running;
        if (i < NODES) {
            g_rowptr[i] = incl - v;
            g_cursor[i] = incl - v;
            if (i == NODES - 1) g_rowptr[NODES] = incl;
        }
        running += wsum[31];
        __syncthreads();
    }
}

__global__ void k_fill(const int* __restrict__ ei) {
    int t = blockIdx.x * blockDim.x + threadIdx.x;
    constexpr int EQ = EDGES / 4;
    if (t < EQ) {
        int e4 = t * 4;
        int4 s = *(const int4*)(ei + e4);
        int4 d = *(const int4*)(ei + EDGES + e4);
        g_csrc[atomicAdd(&g_cursor[d.x], 1)] = s.x;
        g_csrc[atomicAdd(&g_cursor[d.y], 1)] = s.y;
        g_csrc[atomicAdd(&g_cursor[d.z], 1)] = s.z;
        g_csrc[atomicAdd(&g_cursor[d.w], 1)] = s.w;
    } else if (t < EQ + NODES) {
        int i = t - EQ;
        g_csrc[atomicAdd(&g_cursor[i], 1)] = i;
    }
}

// ---------------- fused GATv2 aggregation, layer 1 (H=4, C=64) ----------------
// One warp per node, explicit 2-edge unroll, no max-subtraction.
// Attention input add + LeakyReLU in half2; dot/exp/value-accum in fp32.
__global__ void __launch_bounds__(256) k_agg1(const int* __restrict__ rowptr,
                                              const int* __restrict__ csrc,
                                              const __half* __restrict__ xl,
                                              const __half* __restrict__ xr,
                                              const float* __restrict__ att,
                                              const float* __restrict__ bias,
                                              __half* __restrict__ out) {
    int warp = (blockIdx.x * blockDim.x + threadIdx.x) >> 5;
    int lane = threadIdx.x & 31;
    if (warp >= NODES) return;
    int n = warp;
    int off = lane * 8;

    uint4 rraw = *(const uint4*)(xr + (size_t)n * HC + off);
    __half2 rr2[4];
    *(uint4*)rr2 = rraw;
    const float4* pa = (const float4*)(att + off);
    float4 a0 = pa[0], a1 = pa[1];
    float aw[8] = {a0.x, a0.y, a0.z, a0.w, a1.x, a1.y, a1.z, a1.w};
    const __half2 neg2 = __float2half2_rn(NEG);

    float s = 0.f;
    float acc[8] = {0.f, 0.f, 0.f, 0.f, 0.f, 0.f, 0.f, 0.f};

    int b = rowptr[n], e = rowptr[n + 1];
    for (int kb = b; kb < e; kb += 32) {
        int idx = kb + lane;
        int mysrc = (idx < e) ? csrc[idx] : 0;
        int cnt = min(32, e - kb);
        int j = 0;
        for (; j + 1 < cnt; j += 2) {
            int s0 = __shfl_sync(0xffffffffu, mysrc, j);
            int s1 = __shfl_sync(0xffffffffu, mysrc, j + 1);
            uint4 uraw = *(const uint4*)(xl + (size_t)s0 * HC + off);
            uint4 traw = *(const uint4*)(xl + (size_t)s1 * HC + off);
            __half2* uh = (__half2*)&uraw;
            __half2* th = (__half2*)&traw;
            float q0 = 0.f, q1 = 0.f;
            float uf[8], tf[8];
#pragma unroll
            for (int i = 0; i < 4; i++) {
                float2 lu = __half22float2(lrelu2(__hadd2(uh[i], rr2[i]), neg2));
                float2 lt = __half22float2(lrelu2(__hadd2(th[i], rr2[i]), neg2));
                float2 vu = __half22float2(uh[i]);
                float2 vt = __half22float2(th[i]);
                uf[2 * i] = vu.x; uf[2 * i + 1] = vu.y;
                tf[2 * i] = vt.x; tf[2 * i + 1] = vt.y;
                q0 = fmaf(lu.x, aw[2 * i], q0);
                q0 = fmaf(lu.y, aw[2 * i + 1], q0);
                q1 = fmaf(lt.x, aw[2 * i], q1);
                q1 = fmaf(lt.y, aw[2 * i + 1], q1);
            }
            q0 += __shfl_xor_sync(0xffffffffu, q0, 1);
            q1 += __shfl_xor_sync(0xffffffffu, q1, 1);
            q0 += __shfl_xor_sync(0xffffffffu, q0, 2);
            q1 += __shfl_xor_sync(0xffffffffu, q1, 2);
            q0 += __shfl_xor_sync(0xffffffffu, q0, 4);
            q1 += __shfl_xor_sync(0xffffffffu, q1, 4);
            float w0 = __expf(q0), w1 = __expf(q1);
            s += w0 + w1;
#pragma unroll
            for (int q = 0; q < 8; q++)
                acc[q] += w0 * uf[q] + w1 * tf[q];
        }
        if (j < cnt) {
            int s0 = __shfl_sync(0xffffffffu, mysrc, j);
            uint4 uraw = *(const uint4*)(xl + (size_t)s0 * HC + off);
            __half2* uh = (__half2*)&uraw;
            float q0 = 0.f;
            float uf[8];
#pragma unroll
            for (int i = 0; i < 4; i++) {
                float2 lu = __half22float2(lrelu2(__hadd2(uh[i], rr2[i]), neg2));
                float2 vu = __half22float2(uh[i]);
                uf[2 * i] = vu.x; uf[2 * i + 1] = vu.y;
                q0 = fmaf(lu.x, aw[2 * i], q0);
                q0 = fmaf(lu.y, aw[2 * i + 1], q0);
            }
            q0 += __shfl_xor_sync(0xffffffffu, q0, 1);
            q0 += __shfl_xor_sync(0xffffffffu, q0, 2);
            q0 += __shfl_xor_sync(0xffffffffu, q0, 4);
            float w0 = __expf(q0);
            s += w0;
#pragma unroll
            for (int q = 0; q < 8; q++)
                acc[q] += w0 * uf[q];
        }
    }
    float inv = 1.0f / s;
    const float4* pb = (const float4*)(bias + off);
    float4 b0 = pb[0], b1 = pb[1];
    float bw[8] = {b0.x, b0.y, b0.z, b0.w, b1.x, b1.y, b1.z, b1.w};
    __half hv[8];
#pragma unroll
    for (int q = 0; q < 8; q++)
        hv[q] = __float2half_rn(fmaxf(acc[q] * inv + bw[q], 0.f));
    *(uint4*)(out + (size_t)n * HC + off) = *(uint4*)hv;
}

// ---------------- fused GATv2 aggregation layer 2 + final linear ----------------
// half2 add+lrelu; dot/exp/value in fp32.
__global__ void __launch_bounds__(256) k_agg2(const int* __restrict__ rowptr,
                                              const int* __restrict__ csrc,
                                              const __half* __restrict__ xl,
                                              const __half* __restrict__ xr,
                                              const float* __restrict__ att,
                                              const float* __restrict__ bias,
                                              const float* __restrict__ Wlin,
                                              const float* __restrict__ blin,
                                              float* __restrict__ out) {
    int warp = (blockIdx.x * blockDim.x + threadIdx.x) >> 5;
    int lane = threadIdx.x & 31;
    if (warp >= NODES) return;
    int n = warp;
    int off = lane * 2;

    __half2 rrh = *(const __half2*)(xr + (size_t)n * OUTC + off);
    float2 a = *(const float2*)(att + off);
    const __half2 neg2 = __float2half2_rn(NEG);

    float s = 0.f;
    float acc0 = 0.f, acc1 = 0.f;

    int b = rowptr[n], e = rowptr[n + 1];
    for (int kb = b; kb < e; kb += 32) {
        int idx = kb + lane;
        int mysrc = (idx < e) ? csrc[idx] : 0;
        int cnt = min(32, e - kb);
        int j = 0;
        for (; j + 1 < cnt; j += 2) {
            int s0 = __shfl_sync(0xffffffffu, mysrc, j);
            int s1 = __shfl_sync(0xffffffffu, mysrc, j + 1);
            __half2 uh0 = *(const __half2*)(xl + (size_t)s0 * OUTC + off);
            __half2 uh1 = *(const __half2*)(xl + (size_t)s1 * OUTC + off);
            float2 l0 = __half22float2(lrelu2(__hadd2(uh0, rrh), neg2));
            float2 l1 = __half22float2(lrelu2(__hadd2(uh1, rrh), neg2));
            float2 v0 = __half22float2(uh0);
            float2 v1 = __half22float2(uh1);
            float q0 = l0.x * a.x + l0.y * a.y;
            float q1 = l1.x * a.x + l1.y * a.y;
#pragma unroll
            for (int d = 1; d < 32; d <<= 1) {
                q0 += __shfl_xor_sync(0xffffffffu, q0, d);
                q1 += __shfl_xor_sync(0xffffffffu, q1, d);
            }
            float w0 = __expf(q0), w1 = __expf(q1);
            s += w0 + w1;
            acc0 += w0 * v0.x + w1 * v1.x;
            acc1 += w0 * v0.y + w1 * v1.y;
        }
        if (j < cnt) {
            int s0 = __shfl_sync(0xffffffffu, mysrc, j);
            __half2 uh0 = *(const __half2*)(xl + (size_t)s0 * OUTC + off);
            float2 l0 = __half22float2(lrelu2(__hadd2(uh0, rrh), neg2));
            float2 v0 = __half22float2(uh0);
            float q0 = l0.x * a.x + l0.y * a.y;
#pragma unroll
            for (int d = 1; d < 32; d <<= 1)
                q0 += __shfl_xor_sync(0xffffffffu, q0, d);
            float w0 = __expf(q0);
            s += w0;
            acc0 += w0 * v0.x;
            acc1 += w0 * v0.y;
        }
    }
    float inv = 1.0f / s;
    float2 bb = *(const float2*)(bias + off);
    float hx = fmaxf(acc0 * inv + bb.x, 0.f);
    float hy = fmaxf(acc1 * inv + bb.y, 0.f);

    float part[NC];
#pragma unroll
    for (int c = 0; c < NC; c++)
        part[c] = hx * Wlin[off * NC + c] + hy * Wlin[(off + 1) * NC + c];
#pragma unroll
    for (int d = 16; d >= 1; d >>= 1)
#pragma unroll
        for (int c = 0; c < NC; c++)
            part[c] += __shfl_xor_sync(0xffffffffu, part[c], d);
    if (lane == 0) {
#pragma unroll
        for (int c = 0; c < NC; c++)
            out[(size_t)n * NC + c] = part[c] + blin[c];
    }
}

// ---------------- launch (R13 schedule, unchanged) ----------------
extern "C" void kernel_launch(void* const* d_in, const int* in_sizes, int n_in,
                              void* d_out, int out_size) {
    const float* x    = (const float*)d_in[0];
    const int*   ei   = (const int*)d_in[1];
    const float* Wl1  = (const float*)d_in[2];
    const float* Wr1  = (const float*)d_in[3];
    const float* att1 = (const float*)d_in[4];
    const float* b1   = (const float*)d_in[5];
    const float* Wl2  = (const float*)d_in[6];
    const float* Wr2  = (const float*)d_in[7];
    const float* att2 = (const float*)d_in[8];
    const float* b2   = (const float*)d_in[9];
    const float* Wlin = (const float*)d_in[10];
    const float* blin = (const float*)d_in[11];
    float* out = (float*)d_out;

    __half *xl1, *xr1, *h1, *xl2, *xr2;
    __half *bt1h, *bt1l, *bt2h, *bt2l;
    int *rowptr, *csrc, *deg;
    cudaGetSymbolAddress((void**)&xl1, g_xl1);
    cudaGetSymbolAddress((void**)&xr1, g_xr1);
    cudaGetSymbolAddress((void**)&h1,  g_h1);
    cudaGetSymbolAddress((void**)&xl2, g_xl2);
    cudaGetSymbolAddress((void**)&xr2, g_xr2);
    cudaGetSymbolAddress((void**)&rowptr, g_rowptr);
    cudaGetSymbolAddress((void**)&csrc,   g_csrc);
    cudaGetSymbolAddress((void**)&deg,    g_deg);
    cudaGetSymbolAddress((void**)&bt1h, g_bt1_hi);
    cudaGetSymbolAddress((void**)&bt1l, g_bt1_lo);
    cudaGetSymbolAddress((void**)&bt2h, g_bt2_hi);
    cudaGetSymbolAddress((void**)&bt2l, g_bt2_lo);

    static cudaStream_t s2 = nullptr;
    static cudaEvent_t ev_fork = nullptr, ev_join = nullptr;
    if (!s2) {
        cudaStreamCreateWithFlags(&s2, cudaStreamNonBlocking);
        cudaEventCreateWithFlags(&ev_fork, cudaEventDisableTiming);
        cudaEventCreateWithFlags(&ev_join, cudaEventDisableTiming);
    }

    int mrows = (NODES + 127) / 128;   // 391

    // ---- fork: CSR build + layer-2 weight prep concurrent with prep1+gemm1 ----
    cudaEventRecord(ev_fork, 0);
    cudaStreamWaitEvent(s2, ev_fork, 0);

    cudaMemsetAsync(deg, 0, NODES * sizeof(int), s2);
    k_hist<<<(EDGES / 4 + 255) / 256, 256, 0, s2>>>(ei);
    k_scan_all<<<1, 1024, 0, s2>>>();
    k_fill<<<(EDGES / 4 + NODES + 255) / 256, 256, 0, s2>>>(ei);
    k_prep_B<<<(2 * 64 * 256 + 255) / 256, 256, 0, s2>>>(Wl2, Wr2, bt2h, bt2l, 64, 256);
    cudaEventRecord(ev_join, s2);

    k_prep_B<<<(2 * 256 * 256 + 255) / 256, 256>>>(Wl1, Wr1, bt1h, bt1l, 256, 256);
    gemm_mma<256><<<dim3(4, mrows), 256>>>(x, bt1h, bt1l, xl1, xr1, NODES);

    cudaStreamWaitEvent(0, ev_join, 0);

    k_agg1<<<(NODES + 7) / 8, 256>>>(rowptr, csrc, xl1, xr1, att1, b1, h1);
    gemm_mma<64><<<dim3(1, mrows), 256>>>(h1, bt2h, bt2l, xl2, xr2, NODES);
    k_agg2<<<(NODES + 7) / 8, 256>>>(rowptr, csrc, xl2, xr2, att2, b2, Wlin, blin, out);
}

// round 16
// speedup vs baseline: 1.2165x; 1.0739x over previous
#include <cuda_runtime.h>
#include <cuda_fp16.h>
#include <math.h>
#include <stdint.h>

// ---------------- problem constants ----------------
constexpr int NODES = 50000;
constexpr int EDGES = 800000;
constexpr int E2    = EDGES + NODES;   // 850000
constexpr int OUTC  = 64;
constexpr int HC    = 256;             // 4 heads * 64
constexpr int NC    = 10;
constexpr float NEG = 0.2f;
constexpr int NB_SCAN = (NODES + 1023) / 1024;  // 49

// ---------------- scratch (features in fp16) ----------------
__device__ __half g_xl1[(size_t)NODES * HC];
__device__ __half g_xr1[(size_t)NODES * HC];
__device__ __half g_h1 [(size_t)NODES * HC];
__device__ __half g_xl2[(size_t)NODES * OUTC];
__device__ __half g_xr2[(size_t)NODES * OUTC];
__device__ int   g_deg[NODES];
__device__ int   g_rowptr[NODES + 1];
__device__ int   g_cursor[NODES];
__device__ int   g_csrc[E2];
// transposed fp16 weights: layer1 [512][256], layer2 [128][256]
__device__ __half g_bt1[512 * 256];
__device__ __half g_bt2[128 * 256];

__device__ __forceinline__ float lrelu(float v) { return v > 0.f ? v : NEG * v; }

__device__ __forceinline__ uint32_t smem_u32(const void* p) {
    uint32_t a;
    asm("{ .reg .u64 t; cvta.to.shared.u64 t, %1; cvt.u32.u64 %0, t; }" : "=r"(a) : "l"(p));
    return a;
}

__device__ __forceinline__ void ldsm_x4(uint32_t* r, uint32_t addr) {
    asm volatile("ldmatrix.sync.aligned.m8n8.x4.shared.b16 {%0,%1,%2,%3}, [%4];"
                 : "=r"(r[0]), "=r"(r[1]), "=r"(r[2]), "=r"(r[3]) : "r"(addr));
}
__device__ __forceinline__ void ldsm_x2(uint32_t* r, uint32_t addr) {
    asm volatile("ldmatrix.sync.aligned.m8n8.x2.shared.b16 {%0,%1}, [%2];"
                 : "=r"(r[0]), "=r"(r[1]) : "r"(addr));
}
__device__ __forceinline__ void mma_fp16(float* c, const uint32_t* a, const uint32_t* b) {
    asm volatile("mma.sync.aligned.m16n8k16.row.col.f32.f16.f16.f32 "
                 "{%0,%1,%2,%3}, {%4,%5,%6,%7}, {%8,%9}, {%0,%1,%2,%3};"
                 : "+f"(c[0]), "+f"(c[1]), "+f"(c[2]), "+f"(c[3])
                 : "r"(a[0]), "r"(a[1]), "r"(a[2]), "r"(a[3]), "r"(b[0]), "r"(b[1]));
}

// half2 LeakyReLU (valid for NEG>0: max(v, NEG*v) == lrelu(v))
__device__ __forceinline__ __half2 lrelu2(__half2 v, __half2 neg) {
    return __hmax2(v, __hmul2(v, neg));
}

// ---------------- weight prep: transpose to fp16 ----------------
__global__ void k_prep_B(const float* __restrict__ W0, const float* __restrict__ W1,
                         __half* __restrict__ bt, int N, int K) {
    int t = blockIdx.x * blockDim.x + threadIdx.x;
    int total = 2 * N * K;
    if (t >= total) return;
    int mat = t / (N * K);
    int r = t - mat * (N * K);
    int n = r / K, k = r - n * K;
    const float* W = mat ? W1 : W0;
    bt[t] = __float2half_rn(W[k * N + n]);
}

// ---------------- fp16 tensor-core GEMM (mma.sync), double-buffered ----------------
template <int NBM, typename AT>
__global__ void __launch_bounds__(256, 1) gemm_mma(const AT* __restrict__ A,
                                                   const __half* __restrict__ Bh,
                                                   __half* __restrict__ C0,
                                                   __half* __restrict__ C1,
                                                   int M) {
    constexpr int K = 256;
    constexpr int LDS = 40;
    constexpr int STG = 128 * LDS;           // elements per stage
    constexpr bool AHALF = (sizeof(AT) == 2);
    __shared__ __half sAh[2 * STG];
    __shared__ __half sBh[2 * STG];

    int tid = threadIdx.x;
    int lane = tid & 31;
    int wid = tid >> 5;
    int warpM = wid >> 2;
    int warpN = wid & 3;
    int m0 = blockIdx.y * 128;
    int n0 = blockIdx.x * 128;

    uint32_t bAh = smem_u32(sAh);
    uint32_t bBh = smem_u32(sBh);

    float4 apf[4];
    uint4  apfh[2];
    int4 bhpf[2];

    auto gload = [&](int kb) {
        if constexpr (!AHALF) {
#pragma unroll
            for (int i = 0; i < 4; i++) {
                int u = tid + 256 * i;
                int row = u >> 3, c4 = u & 7;
                apf[i] = make_float4(0.f, 0.f, 0.f, 0.f);
                if (m0 + row < M)
                    apf[i] = *(const float4*)((const float*)A + (size_t)(m0 + row) * K + kb * 32 + c4 * 4);
            }
        } else {
#pragma unroll
            for (int i = 0; i < 2; i++) {
                int u = tid + 256 * i;
                int row = u >> 2, c8 = u & 3;
                apfh[i] = make_uint4(0, 0, 0, 0);
                if (m0 + row < M)
                    apfh[i] = *(const uint4*)((const __half*)A + (size_t)(m0 + row) * K + kb * 32 + c8 * 8);
            }
        }
#pragma unroll
        for (int i = 0; i < 2; i++) {
            int u = tid + 256 * i;
            int row = u >> 2, c = u & 3;
            size_t g = (size_t)(n0 + row) * K + kb * 32 + c * 8;
            bhpf[i] = *(const int4*)(Bh + g);
        }
    };

    auto sstore = [&](int st) {
        int so = st * STG;
        if constexpr (!AHALF) {
#pragma unroll
            for (int i = 0; i < 4; i++) {
                int u = tid + 256 * i;
                int row = u >> 3, c4 = u & 7;
                float4 v = apf[i];
                __half2 h0, h1;
                h0.x = __float2half_rn(v.x);
                h0.y = __float2half_rn(v.y);
                h1.x = __float2half_rn(v.z);
                h1.y = __float2half_rn(v.w);
                int e = so + row * LDS + c4 * 4;
                *(__half2*)(sAh + e)     = h0;
                *(__half2*)(sAh + e + 2) = h1;
            }
        } else {
#pragma unroll
            for (int i = 0; i < 2; i++) {
                int u = tid + 256 * i;
                int row = u >> 2, c8 = u & 3;
                *(uint4*)(sAh + so + row * LDS + c8 * 8) = apfh[i];
            }
        }
#pragma unroll
        for (int i = 0; i < 2; i++) {
            int u = tid + 256 * i;
            int row = u >> 2, c = u & 3;
            *(int4*)(sBh + so + row * LDS + c * 8) = bhpf[i];
        }
    };

    float acc[4][4][4];
#pragma unroll
    for (int f = 0; f < 4; f++)
#pragma unroll
        for (int g = 0; g < 4; g++)
#pragma unroll
            for (int q = 0; q < 4; q++) acc[f][g][q] = 0.f;

    int arow = warpM * 64 + (lane & 15);
    int akc  = (lane >> 4) << 3;
    int brow = warpN * 32 + (lane & 7);
    int bkc  = ((lane >> 3) & 1) << 3;

    gload(0);
    sstore(0);
    __syncthreads();

    for (int kb = 0; kb < 8; kb++) {
        int cur = kb & 1;
        if (kb < 7) gload(kb + 1);

        uint32_t stoff = (uint32_t)(cur * STG * 2);
#pragma unroll
        for (int kk = 0; kk < 2; kk++) {
            uint32_t aoff = stoff + (uint32_t)((arow * LDS + kk * 16 + akc) * 2);
            uint32_t boff = stoff + (uint32_t)((brow * LDS + kk * 16 + bkc) * 2);

            uint32_t ah[4][4], bh[4][2];
#pragma unroll
            for (int f = 0; f < 4; f++)
                ldsm_x4(ah[f], bAh + aoff + (uint32_t)(f * 16 * LDS * 2));
#pragma unroll
            for (int g = 0; g < 4; g++)
                ldsm_x2(bh[g], bBh + boff + (uint32_t)(g * 8 * LDS * 2));
#pragma unroll
            for (int f = 0; f < 4; f++)
#pragma unroll
                for (int g = 0; g < 4; g++)
                    mma_fp16(acc[f][g], ah[f], bh[g]);
        }

        if (kb < 7) sstore((kb + 1) & 1);
        __syncthreads();
    }

#pragma unroll
    for (int f = 0; f < 4; f++) {
#pragma unroll
        for (int g = 0; g < 4; g++) {
            int row = m0 + warpM * 64 + f * 16 + (lane >> 2);
            int col = n0 + warpN * 32 + g * 8 + (lane & 3) * 2;
            int mat = col / NBM;
            int cc = col - mat * NBM;
            __half* Cp = mat ? C1 : C0;
            if (row < M) {
                __half2 v;
                v.x = __float2half_rn(acc[f][g][0]);
                v.y = __float2half_rn(acc[f][g][1]);
                *(__half2*)(Cp + (size_t)row * NBM + cc) = v;
            }
            if (row + 8 < M) {
                __half2 v;
                v.x = __float2half_rn(acc[f][g][2]);
                v.y = __float2half_rn(acc[f][g][3]);
                *(__half2*)(Cp + (size_t)(row + 8) * NBM + cc) = v;
            }
        }
    }
}

// ---------------- CSR build ----------------
__global__ void k_hist(const int* __restrict__ ei) {
    int t = blockIdx.x * blockDim.x + threadIdx.x;
    int e4 = t * 4;
    if (e4 + 3 < EDGES) {
        int4 d = *(const int4*)(ei + EDGES + e4);
        atomicAdd(&g_deg[d.x], 1);
        atomicAdd(&g_deg[d.y], 1);
        atomicAdd(&g_deg[d.z], 1);
        atomicAdd(&g_deg[d.w], 1);
    } else if (e4 < EDGES) {
        for (int e = e4; e < EDGES; e++) atomicAdd(&g_deg[ei[EDGES + e]], 1);
    }
}

__global__ void __launch_bounds__(1024) k_scan_all() {
    __shared__ int wsum[32];
    int tid = threadIdx.x;
    int lane = tid & 31, w = tid >> 5;
    int running = 0;
    for (int chunk = 0; chunk < NB_SCAN; chunk++) {
        int i = chunk * 1024 + tid;
        int v = (i < NODES) ? (g_deg[i] + 1) : 0;   // +1 = self loop
        int x = v;
#pragma unroll
        for (int d = 1; d < 32; d <<= 1) {
            int y = __shfl_up_sync(0xffffffffu, x, d);
            if (lane >= d) x += y;
        }
        if (lane == 31) wsum[w] = x;
        __syncthreads();
        if (w == 0) {
            int tsum = wsum[lane];
#pragma unroll
            for (int d = 1; d < 32; d <<= 1) {
                int y = __shfl_up_sync(0xffffffffu, tsum, d);
                if (lane >= d) tsum += y;
            }
            wsum[lane] = tsum;
        }
        __syncthreads();
        int incl = x + (w > 0 ? wsum[w - 1] : 0) + running;
        if (i < NODES) {
            g_rowptr[i] = incl - v;
            g_cursor[i] = incl - v;
            if (i == NODES - 1) g_rowptr[NODES] = incl;
        }
        running += wsum[31];
        __syncthreads();
    }
}

__global__ void k_fill(const int* __restrict__ ei) {
    int t = blockIdx.x * blockDim.x + threadIdx.x;
    constexpr int EQ = EDGES / 4;
    if (t < EQ) {
        int e4 = t * 4;
        int4 s = *(const int4*)(ei + e4);
        int4 d = *(const int4*)(ei + EDGES + e4);
        g_csrc[atomicAdd(&g_cursor[d.x], 1)] = s.x;
        g_csrc[atomicAdd(&g_cursor[d.y], 1)] = s.y;
        g_csrc[atomicAdd(&g_cursor[d.z], 1)] = s.z;
        g_csrc[atomicAdd(&g_cursor[d.w], 1)] = s.w;
    } else if (t < EQ + NODES) {
        int i = t - EQ;
        g_csrc[atomicAdd(&g_cursor[i], 1)] = i;
    }
}

// ---------------- fused GATv2 aggregation, layer 1 (H=4, C=64) ----------------
// One warp per node, explicit 2-edge unroll, no max-subtraction.
// Attention input add + LeakyReLU in half2; dot/exp/value-accum in fp32.
__global__ void __launch_bounds__(256) k_agg1(const int* __restrict__ rowptr,
                                              const int* __restrict__ csrc,
                                              const __half* __restrict__ xl,
                                              const __half* __restrict__ xr,
                                              const float* __restrict__ att,
                                              const float* __restrict__ bias,
                                              __half* __restrict__ out) {
    int warp = (blockIdx.x * blockDim.x + threadIdx.x) >> 5;
    int lane = threadIdx.x & 31;
    if (warp >= NODES) return;
    int n = warp;
    int off = lane * 8;

    uint4 rraw = *(const uint4*)(xr + (size_t)n * HC + off);
    __half2 rr2[4];
    *(uint4*)rr2 = rraw;
    const float4* pa = (const float4*)(att + off);
    float4 a0 = pa[0], a1 = pa[1];
    float aw[8] = {a0.x, a0.y, a0.z, a0.w, a1.x, a1.y, a1.z, a1.w};
    const __half2 neg2 = __float2half2_rn(NEG);

    float s = 0.f;
    float acc[8] = {0.f, 0.f, 0.f, 0.f, 0.f, 0.f, 0.f, 0.f};

    int b = rowptr[n], e = rowptr[n + 1];
    for (int kb = b; kb < e; kb += 32) {
        int idx = kb + lane;
        int mysrc = (idx < e) ? csrc[idx] : 0;
        int cnt = min(32, e - kb);
        int j = 0;
        for (; j + 1 < cnt; j += 2) {
            int s0 = __shfl_sync(0xffffffffu, mysrc, j);
            int s1 = __shfl_sync(0xffffffffu, mysrc, j + 1);
            uint4 uraw = *(const uint4*)(xl + (size_t)s0 * HC + off);
            uint4 traw = *(const uint4*)(xl + (size_t)s1 * HC + off);
            __half2* uh = (__half2*)&uraw;
            __half2* th = (__half2*)&traw;
            float q0 = 0.f, q1 = 0.f;
            float uf[8], tf[8];
#pragma unroll
            for (int i = 0; i < 4; i++) {
                float2 lu = __half22float2(lrelu2(__hadd2(uh[i], rr2[i]), neg2));
                float2 lt = __half22float2(lrelu2(__hadd2(th[i], rr2[i]), neg2));
                float2 vu = __half22float2(uh[i]);
                float2 vt = __half22float2(th[i]);
                uf[2 * i] = vu.x; uf[2 * i + 1] = vu.y;
                tf[2 * i] = vt.x; tf[2 * i + 1] = vt.y;
                q0 = fmaf(lu.x, aw[2 * i], q0);
                q0 = fmaf(lu.y, aw[2 * i + 1], q0);
                q1 = fmaf(lt.x, aw[2 * i], q1);
                q1 = fmaf(lt.y, aw[2 * i + 1], q1);
            }
            q0 += __shfl_xor_sync(0xffffffffu, q0, 1);
            q1 += __shfl_xor_sync(0xffffffffu, q1, 1);
            q0 += __shfl_xor_sync(0xffffffffu, q0, 2);
            q1 += __shfl_xor_sync(0xffffffffu, q1, 2);
            q0 += __shfl_xor_sync(0xffffffffu, q0, 4);
            q1 += __shfl_xor_sync(0xffffffffu, q1, 4);
            float w0 = __expf(q0), w1 = __expf(q1);
            s += w0 + w1;
#pragma unroll
            for (int q = 0; q < 8; q++)
                acc[q] += w0 * uf[q] + w1 * tf[q];
        }
        if (j < cnt) {
            int s0 = __shfl_sync(0xffffffffu, mysrc, j);
            uint4 uraw = *(const uint4*)(xl + (size_t)s0 * HC + off);
            __half2* uh = (__half2*)&uraw;
            float q0 = 0.f;
            float uf[8];
#pragma unroll
            for (int i = 0; i < 4; i++) {
                float2 lu = __half22float2(lrelu2(__hadd2(uh[i], rr2[i]), neg2));
                float2 vu = __half22float2(uh[i]);
                uf[2 * i] = vu.x; uf[2 * i + 1] = vu.y;
                q0 = fmaf(lu.x, aw[2 * i], q0);
                q0 = fmaf(lu.y, aw[2 * i + 1], q0);
            }
            q0 += __shfl_xor_sync(0xffffffffu, q0, 1);
            q0 += __shfl_xor_sync(0xffffffffu, q0, 2);
            q0 += __shfl_xor_sync(0xffffffffu, q0, 4);
            float w0 = __expf(q0);
            s += w0;
#pragma unroll
            for (int q = 0; q < 8; q++)
                acc[q] += w0 * uf[q];
        }
    }
    float inv = 1.0f / s;
    const float4* pb = (const float4*)(bias + off);
    float4 b0 = pb[0], b1 = pb[1];
    float bw[8] = {b0.x, b0.y, b0.z, b0.w, b1.x, b1.y, b1.z, b1.w};
    __half hv[8];
#pragma unroll
    for (int q = 0; q < 8; q++)
        hv[q] = __float2half_rn(fmaxf(acc[q] * inv + bw[q], 0.f));
    *(uint4*)(out + (size_t)n * HC + off) = *(uint4*)hv;
}

// ---------------- fused GATv2 aggregation layer 2 + final linear ----------------
// half2 add+lrelu; dot/exp/value in fp32.
__global__ void __launch_bounds__(256) k_agg2(const int* __restrict__ rowptr,
                                              const int* __restrict__ csrc,
                                              const __half* __restrict__ xl,
                                              const __half* __restrict__ xr,
                                              const float* __restrict__ att,
                                              const float* __restrict__ bias,
                                              const float* __restrict__ Wlin,
                                              const float* __restrict__ blin,
                                              float* __restrict__ out) {
    int warp = (blockIdx.x * blockDim.x + threadIdx.x) >> 5;
    int lane = threadIdx.x & 31;
    if (warp >= NODES) return;
    int n = warp;
    int off = lane * 2;

    __half2 rrh = *(const __half2*)(xr + (size_t)n * OUTC + off);
    float2 a = *(const float2*)(att + off);
    const __half2 neg2 = __float2half2_rn(NEG);

    float s = 0.f;
    float acc0 = 0.f, acc1 = 0.f;

    int b = rowptr[n], e = rowptr[n + 1];
    for (int kb = b; kb < e; kb += 32) {
        int idx = kb + lane;
        int mysrc = (idx < e) ? csrc[idx] : 0;
        int cnt = min(32, e - kb);
        int j = 0;
        for (; j + 1 < cnt; j += 2) {
            int s0 = __shfl_sync(0xffffffffu, mysrc, j);
            int s1 = __shfl_sync(0xffffffffu, mysrc, j + 1);
            __half2 uh0 = *(const __half2*)(xl + (size_t)s0 * OUTC + off);
            __half2 uh1 = *(const __half2*)(xl + (size_t)s1 * OUTC + off);
            float2 l0 = __half22float2(lrelu2(__hadd2(uh0, rrh), neg2));
            float2 l1 = __half22float2(lrelu2(__hadd2(uh1, rrh), neg2));
            float2 v0 = __half22float2(uh0);
            float2 v1 = __half22float2(uh1);
            float q0 = l0.x * a.x + l0.y * a.y;
            float q1 = l1.x * a.x + l1.y * a.y;
#pragma unroll
            for (int d = 1; d < 32; d <<= 1) {
                q0 += __shfl_xor_sync(0xffffffffu, q0, d);
                q1 += __shfl_xor_sync(0xffffffffu, q1, d);
            }
            float w0 = __expf(q0), w1 = __expf(q1);
            s += w0 + w1;
            acc0 += w0 * v0.x + w1 * v1.x;
            acc1 += w0 * v0.y + w1 * v1.y;
        }
        if (j < cnt) {
            int s0 = __shfl_sync(0xffffffffu, mysrc, j);
            __half2 uh0 = *(const __half2*)(xl + (size_t)s0 * OUTC + off);
            float2 l0 = __half22float2(lrelu2(__hadd2(uh0, rrh), neg2));
            float2 v0 = __half22float2(uh0);
            float q0 = l0.x * a.x + l0.y * a.y;
#pragma unroll
            for (int d = 1; d < 32; d <<= 1)
                q0 += __shfl_xor_sync(0xffffffffu, q0, d);
            float w0 = __expf(q0);
            s += w0;
            acc0 += w0 * v0.x;
            acc1 += w0 * v0.y;
        }
    }
    float inv = 1.0f / s;
    float2 bb = *(const float2*)(bias + off);
    float hx = fmaxf(acc0 * inv + bb.x, 0.f);
    float hy = fmaxf(acc1 * inv + bb.y, 0.f);

    float part[NC];
#pragma unroll
    for (int c = 0; c < NC; c++)
        part[c] = hx * Wlin[off * NC + c] + hy * Wlin[(off + 1) * NC + c];
#pragma unroll
    for (int d = 16; d >= 1; d >>= 1)
#pragma unroll
        for (int c = 0; c < NC; c++)
            part[c] += __shfl_xor_sync(0xffffffffu, part[c], d);
    if (lane == 0) {
#pragma unroll
        for (int c = 0; c < NC; c++)
            out[(size_t)n * NC + c] = part[c] + blin[c];
    }
}

// ---------------- launch (R15 schedule, unchanged) ----------------
extern "C" void kernel_launch(void* const* d_in, const int* in_sizes, int n_in,
                              void* d_out, int out_size) {
    const float* x    = (const float*)d_in[0];
    const int*   ei   = (const int*)d_in[1];
    const float* Wl1  = (const float*)d_in[2];
    const float* Wr1  = (const float*)d_in[3];
    const float* att1 = (const float*)d_in[4];
    const float* b1   = (const float*)d_in[5];
    const float* Wl2  = (const float*)d_in[6];
    const float* Wr2  = (const float*)d_in[7];
    const float* att2 = (const float*)d_in[8];
    const float* b2   = (const float*)d_in[9];
    const float* Wlin = (const float*)d_in[10];
    const float* blin = (const float*)d_in[11];
    float* out = (float*)d_out;

    __half *xl1, *xr1, *h1, *xl2, *xr2;
    __half *bt1, *bt2;
    int *rowptr, *csrc, *deg;
    cudaGetSymbolAddress((void**)&xl1, g_xl1);
    cudaGetSymbolAddress((void**)&xr1, g_xr1);
    cudaGetSymbolAddress((void**)&h1,  g_h1);
    cudaGetSymbolAddress((void**)&xl2, g_xl2);
    cudaGetSymbolAddress((void**)&xr2, g_xr2);
    cudaGetSymbolAddress((void**)&rowptr, g_rowptr);
    cudaGetSymbolAddress((void**)&csrc,   g_csrc);
    cudaGetSymbolAddress((void**)&deg,    g_deg);
    cudaGetSymbolAddress((void**)&bt1, g_bt1);
    cudaGetSymbolAddress((void**)&bt2, g_bt2);

    static cudaStream_t s2 = nullptr;
    static cudaEvent_t ev_fork = nullptr, ev_join = nullptr;
    if (!s2) {
        cudaStreamCreateWithFlags(&s2, cudaStreamNonBlocking);
        cudaEventCreateWithFlags(&ev_fork, cudaEventDisableTiming);
        cudaEventCreateWithFlags(&ev_join, cudaEventDisableTiming);
    }

    int mrows = (NODES + 127) / 128;   // 391

    // ---- fork: CSR build + layer-2 weight prep concurrent with prep1+gemm1 ----
    cudaEventRecord(ev_fork, 0);
    cudaStreamWaitEvent(s2, ev_fork, 0);

    cudaMemsetAsync(deg, 0, NODES * sizeof(int), s2);
    k_hist<<<(EDGES / 4 + 255) / 256, 256, 0, s2>>>(ei);
    k_scan_all<<<1, 1024, 0, s2>>>();
    k_fill<<<(EDGES / 4 + NODES + 255) / 256, 256, 0, s2>>>(ei);
    k_prep_B<<<(2 * 64 * 256 + 255) / 256, 256, 0, s2>>>(Wl2, Wr2, bt2, 64, 256);
    cudaEventRecord(ev_join, s2);

    k_prep_B<<<(2 * 256 * 256 + 255) / 256, 256>>>(Wl1, Wr1, bt1, 256, 256);
    gemm_mma<256><<<dim3(4, mrows), 256>>>(x, bt1, xl1, xr1, NODES);

    cudaStreamWaitEvent(0, ev_join, 0);

    k_agg1<<<(NODES + 7) / 8, 256>>>(rowptr, csrc, xl1, xr1, att1, b1, h1);
    gemm_mma<64><<<dim3(1, mrows), 256>>>(h1, bt2, xl2, xr2, NODES);
    k_agg2<<<(NODES + 7) / 8, 256>>>(rowptr, csrc, xl2, xr2, att2, b2, Wlin, blin, out);
}